// round 13
// baseline (speedup 1.0000x reference)
#include <cuda_runtime.h>
#include <cuda_bf16.h>
#include <cstdint>

// CrossPatchModule closed form:
//   B=4, C=64, H=W=512, PH=PW=8, PN=64, kh=kw=64
//   ph=h>>6, i=h&63, pw=w>>6, j=w&63
//   s = ph*8+pw;  m=(c+s)&63
//   out[b,c,h,w] = x[b,c, (m>>3)*64 + i, (m&7)*64 + j] + abs_pos[c*64+m]
//
// R12: R7 config (write-linear / read-gather, MLP=4 front-batched, streaming
// hints, 26 regs, occ 8) + L2::256B prefetch-width hint on the gather loads.
// Each warp's gather touches a 512B contiguous span; the hint lets LTS batch
// the paired 128B sectors per request at the DRAM command queue.

__device__ __forceinline__ float4 ldcs_pf256(const float4* p) {
    float4 v;
    asm volatile("ld.global.nc.cs.L2::256B.v4.f32 {%0,%1,%2,%3}, [%4];"
                 : "=f"(v.x), "=f"(v.y), "=f"(v.z), "=f"(v.w)
                 : "l"(p));
    return v;
}

__global__ __launch_bounds__(256, 8)
void crosspatch_kernel(const float4* __restrict__ x,
                       const float*  __restrict__ ap,
                       float4*       __restrict__ out)
{
    // 4 float4 per thread at stride 256 float4: each warp access is 32
    // consecutive float4 (512B), fully coalesced on both sides.
    unsigned t0 = blockIdx.x * 1024u + threadIdx.x;

    // k-invariant pieces: t0 + k*256 leaves bits 0..6 unchanged, and a
    // 1024-float4 chunk never straddles an image (65536 % 1024 == 0).
    unsigned w4 = t0 & 127u;
    unsigned pw = w4 >> 4;
    unsigned j4 = w4 & 15u;
    unsigned c  = (t0 >> 16) & 63u;
    unsigned base = (t0 >> 16) << 16;          // ((b*64+c) image) * 65536

    unsigned src[4];
    float    add[4];

#pragma unroll
    for (int k = 0; k < 4; ++k) {
        unsigned h  = ((t0 + k * 256u) >> 7) & 511u;
        unsigned ph = h >> 6;
        unsigned i  = h & 63u;

        unsigned m  = (c + ph * 8u + pw) & 63u;
        unsigned src_h  = ((m >> 3) << 6) | i;
        unsigned src_w4 = ((m & 7u) << 4) | j4;

        src[k] = base + (src_h << 7) + src_w4;
        add[k] = __ldg(&ap[(c << 6) | m]);
    }

    float4 v[4];
#pragma unroll
    for (int k = 0; k < 4; ++k)
        v[k] = ldcs_pf256(&x[src[k]]);         // streaming gather + 256B hint

#pragma unroll
    for (int k = 0; k < 4; ++k) {
        float a = add[k];
        v[k].x += a; v[k].y += a; v[k].z += a; v[k].w += a;
        __stcs(&out[t0 + k * 256u], v[k]);     // sequential streaming write
    }
}

extern "C" void kernel_launch(void* const* d_in, const int* in_sizes, int n_in,
                              void* d_out, int out_size)
{
    const float4* x   = (const float4*)d_in[0];   // (4,64,512,512) fp32
    const float*  ap  = (const float*)d_in[1];    // (1,1,64,64,1,1) fp32
    float4*       out = (float4*)d_out;

    crosspatch_kernel<<<16384, 256>>>(x, ap, out);
}

// round 14
// speedup vs baseline: 1.0031x; 1.0031x over previous
#include <cuda_runtime.h>
#include <cuda_bf16.h>
#include <cstdint>

// CrossPatchModule closed form:
//   B=4, C=64, H=W=512, PH=PW=8, PN=64, kh=kw=64
//   ph=h>>6, i=h&63, pw=w>>6, j=w&63
//   s = ph*8+pw;  m=(c+s)&63
//   out[b,c,h,w] = x[b,c, (m>>3)*64 + i, (m&7)*64 + j] + abs_pos[c*64+m]
//
// FINAL (R7 config, restored after R12's L2-hint regression): pure
// permutation gather + scalar add, 512MB irreducible traffic, HBM-bound at
// the measured mixed-R/W ceiling (~6.5 TB/s, DRAM 82%).
//   - write-linear / read-gather orientation (best of both measured)
//   - MLP=4 per thread, all loads front-batched (optimum of MLP 1/4/6/8)
//   - streaming (.cs) load+store hints, plain .128 width (L2::256B regressed)
//   - k-invariant index ALU hoisted; 26 regs, 8 CTAs/SM
// All other axes (persistent grid, occupancy trades, prefetch hints)
// measured neutral-or-worse. This is the machine floor for this problem.

__global__ __launch_bounds__(256, 8)
void crosspatch_kernel(const float4* __restrict__ x,
                       const float*  __restrict__ ap,
                       float4*       __restrict__ out)
{
    // 4 float4 per thread at stride 256 float4: each warp access is 32
    // consecutive float4 (512B), fully coalesced on both sides.
    unsigned t0 = blockIdx.x * 1024u + threadIdx.x;

    // k-invariant pieces: t0 + k*256 leaves bits 0..6 unchanged, and a
    // 1024-float4 chunk never straddles an image (65536 % 1024 == 0),
    // so c and base are constant across the 4 elements.
    unsigned w4 = t0 & 127u;
    unsigned pw = w4 >> 4;
    unsigned j4 = w4 & 15u;
    unsigned c  = (t0 >> 16) & 63u;
    unsigned base = (t0 >> 16) << 16;          // ((b*64+c) image) * 65536

    unsigned src[4];
    float    add[4];

#pragma unroll
    for (int k = 0; k < 4; ++k) {
        unsigned h  = ((t0 + k * 256u) >> 7) & 511u;
        unsigned ph = h >> 6;
        unsigned i  = h & 63u;

        unsigned m  = (c + ph * 8u + pw) & 63u;
        unsigned src_h  = ((m >> 3) << 6) | i;
        unsigned src_w4 = ((m & 7u) << 4) | j4;

        src[k] = base + (src_h << 7) + src_w4;
        add[k] = __ldg(&ap[(c << 6) | m]);
    }

    float4 v[4];
#pragma unroll
    for (int k = 0; k < 4; ++k)
        v[k] = __ldcs(&x[src[k]]);             // streaming gather (no reuse)

#pragma unroll
    for (int k = 0; k < 4; ++k) {
        float a = add[k];
        v[k].x += a; v[k].y += a; v[k].z += a; v[k].w += a;
        __stcs(&out[t0 + k * 256u], v[k]);     // sequential streaming write
    }
}

extern "C" void kernel_launch(void* const* d_in, const int* in_sizes, int n_in,
                              void* d_out, int out_size)
{
    const float4* x   = (const float4*)d_in[0];   // (4,64,512,512) fp32
    const float*  ap  = (const float*)d_in[1];    // (1,1,64,64,1,1) fp32
    float4*       out = (float4*)d_out;

    crosspatch_kernel<<<16384, 256>>>(x, ap, out);
}